// round 14
// baseline (speedup 1.0000x reference)
#include <cuda_runtime.h>
#include <cstdint>

// OptFP_Embedding: out[b,f,:] = beta + sum_i c_i(g) * clip(rint((W[x]-beta)*ia_i), lo_i, hi_i)
//   c_i = softmax(gamma)_i * (|alpha_i|+eps); sum_i softmax = 1 folds beta out.
//
// Strategy: TMA BULK GATHER. Route row gathers through the bulk-copy engine
//   (cp.async.bulk.shared::cta.global, UBLKCP) instead of the LDG/L1tex path:
//   one 256B bulk copy per token row, completion via mbarrier expect_tx.
//   Tests whether the ~2.4TB/s gather ceiling is LDG-path miss tracking
//   (TMA path has independent queueing) or raw HBM random efficiency.
//   4 pipeline groups of 32 tokens: compute group g overlaps flight of g+1..3.
//
// Inputs (metadata order):
//   d_in[0] = x           int32   [4096*39]
//   d_in[1] = weight      float32 [1000000*64]
//   d_in[2] = group_index int32   [1000000]
//   d_in[3] = gamma       float32 [8*1*3]
//   d_in[4] = alpha       float32 [3]
//   d_in[5] = beta        float32 [64]
// Output: float32 [4096*39*64]

#define EMB_DIM 64
#define GROUPS 8
#define NBITS 3
#define TPT 16                     // threads per token in compute phase
#define BLOCK_THREADS 256
#define TOKENS_PER_BLOCK 128       // 159744 = 1248 * 128 exactly
#define PGROUPS 4                  // mbarrier pipeline groups
#define GTOK (TOKENS_PER_BLOCK / PGROUPS)   // 32 tokens per group
#define GROUP_BYTES (GTOK * EMB_DIM * 4)    // 8192 B per group

__device__ __forceinline__ uint32_t smem_u32(const void* p) {
    return (uint32_t)__cvta_generic_to_shared(p);
}

__device__ __forceinline__ void mbar_init(uint32_t mbar, uint32_t count) {
    asm volatile("mbarrier.init.shared.b64 [%0], %1;" :: "r"(mbar), "r"(count) : "memory");
}

__device__ __forceinline__ void mbar_arrive_expect_tx(uint32_t mbar, uint32_t bytes) {
    asm volatile("mbarrier.arrive.expect_tx.shared.b64 _, [%0], %1;"
                 :: "r"(mbar), "r"(bytes) : "memory");
}

__device__ __forceinline__ void mbar_wait_parity0(uint32_t mbar) {
    asm volatile(
        "{\n\t"
        ".reg .pred P;\n\t"
        "WAIT_%=:\n\t"
        "mbarrier.try_wait.parity.acquire.cta.shared::cta.b64 P, [%0], 0, 0x989680;\n\t"
        "@P bra.uni DONE_%=;\n\t"
        "bra.uni WAIT_%=;\n\t"
        "DONE_%=:\n\t"
        "}" :: "r"(mbar) : "memory");
}

__device__ __forceinline__ void bulk_copy_256(uint32_t smem_dst, const void* gsrc,
                                              uint32_t mbar) {
    asm volatile(
        "cp.async.bulk.shared::cta.global.mbarrier::complete_tx::bytes [%0], [%1], %2, [%3];"
        :: "r"(smem_dst), "l"(gsrc), "r"(256u), "r"(mbar) : "memory");
}

__global__ __launch_bounds__(BLOCK_THREADS, 6)
void optfp_embedding_kernel(const int* __restrict__ x,
                            const float* __restrict__ weight,
                            const int* __restrict__ group_index,
                            const float* __restrict__ gamma,
                            const float* __restrict__ alpha,
                            const float* __restrict__ beta,
                            float* __restrict__ out,
                            int ntok) {
    __shared__ __align__(256) float4 s_rows[TOKENS_PER_BLOCK][TPT];  // 32 KB
    __shared__ __align__(8) uint64_t s_mbar[PGROUPS];
    __shared__ int s_g[TOKENS_PER_BLOCK];
    __shared__ float s_beta[EMB_DIM];
    __shared__ float s_c[GROUPS][NBITS];    // softmax(gamma)_i * (|alpha_i|+eps)
    __shared__ float s_ia[NBITS];           // 1 / (|alpha_i| + eps)

    const int tid = threadIdx.x;
    const unsigned base0 = (unsigned)blockIdx.x * TOKENS_PER_BLOCK;

    // ---- barrier init + expect_tx (one thread) ----
    if (tid == 0) {
#pragma unroll
        for (int gb = 0; gb < PGROUPS; gb++) {
            const uint32_t mb = smem_u32(&s_mbar[gb]);
            mbar_init(mb, 1);
            mbar_arrive_expect_tx(mb, GROUP_BYTES);
        }
    }

    // ---- one-time coefficient tables ----
    if (tid >= 128 && tid < 128 + EMB_DIM) s_beta[tid - 128] = beta[tid - 128];
    if (tid >= 192 && tid < 192 + GROUPS) {
        const int r = tid - 192;
        // TAU = 1.0
        float g0 = gamma[r * NBITS + 0];
        float g1 = gamma[r * NBITS + 1];
        float g2 = gamma[r * NBITS + 2];
        float m = fmaxf(g0, fmaxf(g1, g2));
        float e0 = __expf(g0 - m);
        float e1 = __expf(g1 - m);
        float e2 = __expf(g2 - m);
        float inv = 1.0f / (e0 + e1 + e2);
        s_c[r][0] = e0 * inv * (fabsf(alpha[0]) + 1e-10f);
        s_c[r][1] = e1 * inv * (fabsf(alpha[1]) + 1e-10f);
        s_c[r][2] = e2 * inv * (fabsf(alpha[2]) + 1e-10f);
        if (r == 0) {
            s_ia[0] = 1.0f / (fabsf(alpha[0]) + 1e-10f);
            s_ia[1] = 1.0f / (fabsf(alpha[1]) + 1e-10f);
            s_ia[2] = 1.0f / (fabsf(alpha[2]) + 1e-10f);
        }
    }

    // ---- index + group gather (threads 0..127, one token each) ----
    int myidx = 0;
    if (tid < TOKENS_PER_BLOCK) {
        const unsigned tok = base0 + (unsigned)tid;
        myidx = (tok < (unsigned)ntok) ? __ldg(x + tok) : 0;
        s_g[tid] = __ldg(group_index + myidx);
    }

    // barriers initialized + expect_tx set before ANY bulk copy can complete
    __syncthreads();

    // ---- issue 128 bulk row copies (256B each) through the TMA/BLKCP path ----
    if (tid < TOKENS_PER_BLOCK) {
        const uint32_t dst = smem_u32(&s_rows[tid][0]);
        const void* src = weight + ((size_t)(unsigned)myidx << 6);
        const uint32_t mb = smem_u32(&s_mbar[tid / GTOK]);
        bulk_copy_256(dst, src, mb);
    }

    const int sub  = tid >> 4;            // 0..15
    const int lane = tid & (TPT - 1);     // 0..15
    const float4 b4 = ((const float4*)s_beta)[lane];
    const float ia0 = s_ia[0], ia1 = s_ia[1], ia2 = s_ia[2];

    // ---- pipelined drain: wait group g, compute its 32 tokens ----
#pragma unroll
    for (int gb = 0; gb < PGROUPS; gb++) {
        mbar_wait_parity0(smem_u32(&s_mbar[gb]));

#pragma unroll
        for (int pass = 0; pass < 2; pass++) {
            const int tl = gb * GTOK + pass * 16 + sub;   // local token 0..127
            const unsigned tok = base0 + (unsigned)tl;
            if (tok >= (unsigned)ntok) continue;

            const float4 w = s_rows[tl][lane];
            const int g = s_g[tl];
            const float c0 = s_c[g][0];
            const float c1 = s_c[g][1];
            const float c2 = s_c[g][2];

            const float wv[4] = {w.x, w.y, w.z, w.w};
            const float bv[4] = {b4.x, b4.y, b4.z, b4.w};
            float rv[4];
#pragma unroll
            for (int c = 0; c < 4; c++) {
                const float wb = wv[c] - bv[c];
                const float r0 = fminf(fmaxf(rintf(wb * ia0),   -2.0f),   1.0f);
                const float r1 = fminf(fmaxf(rintf(wb * ia1),   -8.0f),   7.0f);
                const float r2 = fminf(fmaxf(rintf(wb * ia2), -128.0f), 127.0f);
                float acc = fmaf(c0, r0, bv[c]);
                acc = fmaf(c1, r1, acc);
                rv[c] = fmaf(c2, r2, acc);
            }
            float4 r; r.x = rv[0]; r.y = rv[1]; r.z = rv[2]; r.w = rv[3];
            __stcs((float4*)out + tok * TPT + lane, r);
        }
    }
}

extern "C" void kernel_launch(void* const* d_in, const int* in_sizes, int n_in,
                              void* d_out, int out_size) {
    const int*   x           = (const int*)d_in[0];
    const float* weight      = (const float*)d_in[1];
    const int*   group_index = (const int*)d_in[2];
    const float* gamma       = (const float*)d_in[3];
    const float* alpha       = (const float*)d_in[4];
    const float* beta        = (const float*)d_in[5];
    float* out = (float*)d_out;

    const int ntok = in_sizes[0];  // 4096 * 39 = 159744 = 1248 * 128
    const int blocks = (ntok + TOKENS_PER_BLOCK - 1) / TOKENS_PER_BLOCK;
    optfp_embedding_kernel<<<blocks, BLOCK_THREADS>>>(
        x, weight, group_index, gamma, alpha, beta, out, ntok);
}

// round 17
// speedup vs baseline: 1.0017x; 1.0017x over previous
#include <cuda_runtime.h>
#include <cuda_pipeline.h>
#include <cstdint>

// OptFP_Embedding: out[b,f,:] = beta + sum_i c_i(g) * clip(rint((W[x]-beta)*ia_i), lo_i, hi_i)
//   c_i = softmax(gamma)_i * (|alpha_i|+eps); sum_i softmax = 1 folds beta out.
//
// Strategy: R10 structure (cp.async depth-6 self-staging, best @16.38us) with the
// compute path rebuilt for minimum issue slots at the gather-bandwidth floor:
//   - rintf (FRND, slow conversion pipe) -> magic-constant round-half-even:
//       t = wa + 1.5*2^23 ; clamp t in INTEGER domain (bit patterns monotone) ;
//       r = t - 1.5*2^23
//   - wa-compute and accumulate use packed fma.rn.f32x2 / add.rn.f32x2
//     (sm_100a packed pipe; scalar fallback if feature macro absent).
//
// Inputs (metadata order):
//   d_in[0] = x           int32   [4096*39]
//   d_in[1] = weight      float32 [1000000*64]
//   d_in[2] = group_index int32   [1000000]
//   d_in[3] = gamma       float32 [8*1*3]
//   d_in[4] = alpha       float32 [3]
//   d_in[5] = beta        float32 [64]
// Output: float32 [4096*39*64]

#define EMB_DIM 64
#define GROUPS 8
#define NBITS 3
#define TPT 16                    // threads per token (16 x float4 = 64 floats)
#define BLOCK_THREADS 256
#define SUBS (BLOCK_THREADS / TPT)        // 16 tokens per stage
#define STAGES 6                          // cp.async pipeline depth
#define TOKENS_PER_BLOCK (SUBS * STAGES)  // 96

#define MAGICF 12582912.0f                // 1.5 * 2^23

#if defined(__CUDA_ARCH_FEAT_SM100_ALL) || defined(__CUDA_ARCH_FEAT_SM103_ALL)
#define HAVE_F32X2 1
#endif

__device__ __forceinline__ uint64_t pack2(float x, float y) {
    return ((uint64_t)__float_as_uint(y) << 32) | (uint64_t)__float_as_uint(x);
}
__device__ __forceinline__ uint64_t pack2d(float v) { return pack2(v, v); }
__device__ __forceinline__ float lo2(uint64_t v) { return __uint_as_float((uint32_t)v); }
__device__ __forceinline__ float hi2(uint64_t v) { return __uint_as_float((uint32_t)(v >> 32)); }

__device__ __forceinline__ uint64_t fma2_(uint64_t a, uint64_t b, uint64_t c) {
#ifdef HAVE_F32X2
    uint64_t d;
    asm("fma.rn.f32x2 %0, %1, %2, %3;" : "=l"(d) : "l"(a), "l"(b), "l"(c));
    return d;
#else
    return pack2(fmaf(lo2(a), lo2(b), lo2(c)), fmaf(hi2(a), hi2(b), hi2(c)));
#endif
}
__device__ __forceinline__ uint64_t add2_(uint64_t a, uint64_t b) {
#ifdef HAVE_F32X2
    uint64_t d;
    asm("add.rn.f32x2 %0, %1, %2;" : "=l"(d) : "l"(a), "l"(b));
    return d;
#else
    return pack2(__fadd_rn(lo2(a), lo2(b)), __fadd_rn(hi2(a), hi2(b)));
#endif
}
// integer-domain clamp of (wa + MAGIC): bit patterns in [MAGIC-2^22, MAGIC+2^22]
// share the exponent -> monotone as signed ints
__device__ __forceinline__ uint64_t clamp2i(uint64_t t, int lob, int hib) {
    int l = (int)(uint32_t)t;
    int h = (int)(uint32_t)(t >> 32);
    l = min(max(l, lob), hib);
    h = min(max(h, lob), hib);
    return ((uint64_t)(uint32_t)h << 32) | (uint64_t)(uint32_t)l;
}

// one bitwidth's contribution for a packed element pair:
// acc += c * ( clip(round(w*ia + nb)) )
__device__ __forceinline__ uint64_t qstep(uint64_t w, uint64_t iad, uint64_t nb,
                                          int lob, int hib, uint64_t cd,
                                          uint64_t MP, uint64_t NMP, uint64_t acc) {
    uint64_t t = fma2_(w, iad, nb);     // wa (single-rounded)
    t = add2_(t, MP);                   // round-half-even into mantissa
    t = clamp2i(t, lob, hib);           // clip in integer domain
    t = add2_(t, NMP);                  // back to small float
    return fma2_(cd, t, acc);
}

__global__ __launch_bounds__(BLOCK_THREADS, 6)
void optfp_embedding_kernel(const int* __restrict__ x,
                            const float* __restrict__ weight,
                            const int* __restrict__ group_index,
                            const float* __restrict__ gamma,
                            const float* __restrict__ alpha,
                            const float* __restrict__ beta,
                            float* __restrict__ out,
                            int ntok) {
    __shared__ float4 s_rows[STAGES][BLOCK_THREADS];   // 24 KB staging
    __shared__ float s_beta[EMB_DIM];
    __shared__ float s_nbia[NBITS][EMB_DIM];  // -beta[e] * ia_i
    __shared__ float s_c[GROUPS][NBITS];      // softmax(gamma)_i * (|alpha_i|+eps)
    __shared__ float s_ia[NBITS];             // 1 / (|alpha_i| + eps)

    const int tid = threadIdx.x;

    // ---- one-time coefficient tables (no cross-dependency: one barrier) ----
    if (tid < EMB_DIM) {
        const float b = beta[tid];
        s_beta[tid] = b;
        const float a0 = fabsf(alpha[0]) + 1e-10f;
        const float a1 = fabsf(alpha[1]) + 1e-10f;
        const float a2 = fabsf(alpha[2]) + 1e-10f;
        s_nbia[0][tid] = -b / a0;
        s_nbia[1][tid] = -b / a1;
        s_nbia[2][tid] = -b / a2;
        if (tid < NBITS) s_ia[tid] = 1.0f / (fabsf(alpha[tid]) + 1e-10f);
    }
    if (tid >= 64 && tid < 64 + GROUPS) {
        const int r = tid - 64;
        // TAU = 1.0
        float g0 = gamma[r * NBITS + 0];
        float g1 = gamma[r * NBITS + 1];
        float g2 = gamma[r * NBITS + 2];
        float m = fmaxf(g0, fmaxf(g1, g2));
        float e0 = __expf(g0 - m);
        float e1 = __expf(g1 - m);
        float e2 = __expf(g2 - m);
        float inv = 1.0f / (e0 + e1 + e2);
        s_c[r][0] = e0 * inv * (fabsf(alpha[0]) + 1e-10f);
        s_c[r][1] = e1 * inv * (fabsf(alpha[1]) + 1e-10f);
        s_c[r][2] = e2 * inv * (fabsf(alpha[2]) + 1e-10f);
    }

    const int sub  = tid >> 4;            // 0..15 : token slot within a stage
    const int lane = tid & (TPT - 1);     // 0..15 : 16B chunk within a row

    const unsigned base = (unsigned)blockIdx.x * TOKENS_PER_BLOCK + sub;

    // ---- prologue: front-batched index gathers ----
    int idx[STAGES];
#pragma unroll
    for (int s = 0; s < STAGES; s++) {
        const unsigned tok = base + (unsigned)s * SUBS;
        idx[s] = (tok < (unsigned)ntok) ? __ldg(x + tok) : 0;
    }

    // group ids packed into one register (4-bit fields)
    unsigned gpack = 0;
#pragma unroll
    for (int s = 0; s < STAGES; s++)
        gpack |= ((unsigned)__ldg(group_index + idx[s])) << (s * 4);

    // tables visible before staging traffic starts
    __syncthreads();

    // ---- issue depth-6 cp.async row gathers (16B per thread per stage) ----
#pragma unroll
    for (int s = 0; s < STAGES; s++) {
        __pipeline_memcpy_async(&s_rows[s][tid],
                                (const float4*)weight + (((unsigned)idx[s]) << 4) + lane,
                                sizeof(float4));
        __pipeline_commit();
    }

    // ---- hoisted per-lane packed constants ----
    const float4 b4 = ((const float4*)s_beta)[lane];
    const uint64_t b01 = pack2(b4.x, b4.y), b23 = pack2(b4.z, b4.w);
    const float4 n0 = ((const float4*)s_nbia[0])[lane];
    const float4 n1 = ((const float4*)s_nbia[1])[lane];
    const float4 n2 = ((const float4*)s_nbia[2])[lane];
    const uint64_t n0a = pack2(n0.x, n0.y), n0b = pack2(n0.z, n0.w);
    const uint64_t n1a = pack2(n1.x, n1.y), n1b = pack2(n1.z, n1.w);
    const uint64_t n2a = pack2(n2.x, n2.y), n2b = pack2(n2.z, n2.w);
    const uint64_t MP  = pack2d(MAGICF);
    const uint64_t NMP = pack2d(-MAGICF);

    // integer-domain clamp bounds (compile-time constants)
    const int B2L = __float_as_int(MAGICF - 2.0f),   B2H = __float_as_int(MAGICF + 1.0f);
    const int B4L = __float_as_int(MAGICF - 8.0f),   B4H = __float_as_int(MAGICF + 7.0f);
    const int B8L = __float_as_int(MAGICF - 128.0f), B8H = __float_as_int(MAGICF + 127.0f);

    // ---- drain pipeline: compute one stage as each copy lands ----
#pragma unroll
    for (int s = 0; s < STAGES; s++) {
        __pipeline_wait_prior(STAGES - 1 - s);
        const unsigned tok = base + (unsigned)s * SUBS;
        if (tok >= (unsigned)ntok) continue;

        const float4 w = s_rows[s][tid];
        const uint64_t w01 = pack2(w.x, w.y), w23 = pack2(w.z, w.w);

        const int g = (gpack >> (s * 4)) & 7;
        const uint64_t iad0 = pack2d(s_ia[0]);
        const uint64_t iad1 = pack2d(s_ia[1]);
        const uint64_t iad2 = pack2d(s_ia[2]);
        const uint64_t c0d = pack2d(s_c[g][0]);
        const uint64_t c1d = pack2d(s_c[g][1]);
        const uint64_t c2d = pack2d(s_c[g][2]);

        uint64_t acc01 = b01, acc23 = b23;
        acc01 = qstep(w01, iad0, n0a, B2L, B2H, c0d, MP, NMP, acc01);
        acc23 = qstep(w23, iad0, n0b, B2L, B2H, c0d, MP, NMP, acc23);
        acc01 = qstep(w01, iad1, n1a, B4L, B4H, c1d, MP, NMP, acc01);
        acc23 = qstep(w23, iad1, n1b, B4L, B4H, c1d, MP, NMP, acc23);
        acc01 = qstep(w01, iad2, n2a, B8L, B8H, c2d, MP, NMP, acc01);
        acc23 = qstep(w23, iad2, n2b, B8L, B8H, c2d, MP, NMP, acc23);

        float4 r;
        r.x = lo2(acc01); r.y = hi2(acc01);
        r.z = lo2(acc23); r.w = hi2(acc23);
        __stcs((float4*)out + tok * TPT + lane, r);
    }
}

extern "C" void kernel_launch(void* const* d_in, const int* in_sizes, int n_in,
                              void* d_out, int out_size) {
    const int*   x           = (const int*)d_in[0];
    const float* weight      = (const float*)d_in[1];
    const int*   group_index = (const int*)d_in[2];
    const float* gamma       = (const float*)d_in[3];
    const float* alpha       = (const float*)d_in[4];
    const float* beta        = (const float*)d_in[5];
    float* out = (float*)d_out;

    const int ntok = in_sizes[0];  // 4096 * 39 = 159744 = 96 * 1664
    const int blocks = (ntok + TOKENS_PER_BLOCK - 1) / TOKENS_PER_BLOCK;
    optfp_embedding_kernel<<<blocks, BLOCK_THREADS>>>(
        x, weight, group_index, gamma, alpha, beta, out, ntok);
}